// round 15
// baseline (speedup 1.0000x reference)
#include <cuda_runtime.h>

// Problem shape (fixed for this dataset)
#define N_NODES 400000
#define K_DOWN  5
#define NCONTRIB (N_NODES * K_DOWN)   // 2,000,000
#define F_DIM   128
#define NUP     100000
#define CAP     32                    // bucket capacity per destination
#define UNSEL   (-2147483647 - 1)     // INT_MIN: counter value for unselected rows
#define UPW     4                     // outputs per warp in the gather
#define TPB     256                   // 8 warps per block

// Scratch (allocation-free rule: __device__ globals)
// entry = (w:f32 << 32) | src:u32 ; 400k * 32 * 8B = 102.4 MB
__device__ unsigned long long g_ent[(size_t)N_NODES * CAP];
__device__ int                g_cnt[N_NODES];

// ---------------------------------------------------------------------------
// K0: reset counters to INT_MIN ("not selected"). 1.6 MB of int4 stores.
__global__ void k_clear_cnt() {
    int i = blockIdx.x * blockDim.x + threadIdx.x;
    const int n4 = N_NODES / 4;
    if (i < n4) ((int4*)g_cnt)[i] = make_int4(UNSEL, UNSEL, UNSEL, UNSEL);
}

// K1: mark selected destinations: counter -> 0. Duplicate writes benign.
__global__ void k_mark(const int* __restrict__ sel) {
    int t = blockIdx.x * blockDim.x + threadIdx.x;
    if (t >= NUP) return;
    int s = sel[t];
    if (s >= 0 && s < N_NODES) g_cnt[s] = 0;
}

// K2: bucket fill — thread per (n,k) contribution. ONE 32-bit atomic per
// contribution; slot >= 0 only for selected destinations (unselected
// counters start at INT_MIN), so ~78% of scattered stores are skipped.
__global__ void k_fill(const float* __restrict__ wdn,
                       const int*   __restrict__ nidx) {
    int t = blockIdx.x * blockDim.x + threadIdx.x;
    if (t >= NCONTRIB) return;
    int dst = nidx[t];
    if (dst < 0 || dst >= N_NODES) return;
    int pos = atomicAdd(&g_cnt[dst], 1);
    if (pos >= 0 && pos < CAP) {
        float w  = wdn[t];
        int src  = t / K_DOWN;
        unsigned long long e =
            ((unsigned long long)__float_as_uint(w) << 32) | (unsigned int)src;
        g_ent[(size_t)dst * CAP + pos] = e;
    }
}

// K3: fused gather + normalize — FOUR output rows per warp (round-12 proven
// structure). Changes vs round 12:
//  * bucket entries staged in SMEM: uniform LDS.64 broadcast replaces 64
//    SHFL.32 per warp -> frees issue slots for the load stream
//  * feature loads via __ldcg (no L1 allocation; random rows have no reuse)
// Dead slots (j >= c_i) read row 0 (L1/L2-hot) with weight 0 — unconditional
// load batch, the form that round 14 proved must NOT be predicated.
__global__ void k_gather_fused(const int*   __restrict__ sel,
                               const float* __restrict__ feat,
                               float*       __restrict__ out) {
    __shared__ unsigned long long sh_ev[TPB / 32][32];

    int warp = (blockIdx.x * blockDim.x + threadIdx.x) >> 5;
    int u0 = warp * UPW;
    if (u0 >= NUP) return;
    int lane = threadIdx.x & 31;
    int wib  = (threadIdx.x >> 5);
    int grp  = lane >> 3;          // which of the 4 outputs this lane serves
    int slot = lane & 7;           // bucket slot 0..7

    // uniform scalar loads: all lanes hold all four (s, c)
    int s[UPW], c[UPW];
    #pragma unroll
    for (int i = 0; i < UPW; i++) {
        int u = u0 + i;
        int sv = (u < NUP) ? sel[u] : -1;
        s[i] = (sv >= 0 && sv < N_NODES) ? sv : -1;
    }
    #pragma unroll
    for (int i = 0; i < UPW; i++) {
        int cv = (s[i] >= 0) ? g_cnt[s[i]] : 0;
        if (cv < 0)   cv = 0;
        if (cv > CAP) cv = CAP;
        c[i] = cv;
    }

    // one coalesced trip: slots 0..7 of all four buckets -> stage in SMEM
    int sg = s[grp];
    unsigned long long ev = (sg >= 0)
        ? __ldcs(g_ent + (size_t)sg * CAP + slot) : 0ull;
    sh_ev[wib][lane] = ev;
    __syncwarp();

    const float4* feat4 = (const float4*)feat;
    float  wsum[UPW];
    float4 acc [UPW];
    #pragma unroll
    for (int i = 0; i < UPW; i++) {
        wsum[i] = 0.0f;
        acc[i]  = make_float4(0.f, 0.f, 0.f, 0.f);
    }

    #pragma unroll
    for (int j = 0; j < 8; j++) {
        float  wj[UPW];
        float4 f [UPW];
        #pragma unroll
        for (int i = 0; i < UPW; i++) {
            unsigned long long e = sh_ev[wib][i * 8 + j];  // LDS.64 broadcast
            bool v  = (j < c[i]);
            int  sj = v ? (int)(unsigned int)(e & 0xffffffffull) : 0;
            wj[i]   = v ? __uint_as_float((unsigned int)(e >> 32)) : 0.0f;
            f[i]    = __ldcg(feat4 + (size_t)sj * (F_DIM / 4) + lane);
        }
        #pragma unroll
        for (int i = 0; i < UPW; i++) {
            wsum[i] += wj[i];
            acc[i].x = fmaf(wj[i], f[i].x, acc[i].x);
            acc[i].y = fmaf(wj[i], f[i].y, acc[i].y);
            acc[i].z = fmaf(wj[i], f[i].z, acc[i].z);
            acc[i].w = fmaf(wj[i], f[i].w, acc[i].w);
        }
    }

    // rare tail: c > 8 (P ~ 7% per output)
    #pragma unroll
    for (int i = 0; i < UPW; i++) {
        if (c[i] > 8) {
            const unsigned long long* bucket = g_ent + (size_t)s[i] * CAP;
            for (int j = 8; j < c[i]; j++) {
                unsigned long long e = __ldcs(bucket + j);  // uniform broadcast
                int   sj = (int)(unsigned int)(e & 0xffffffffull);
                float w  = __uint_as_float((unsigned int)(e >> 32));
                float4 ft = __ldcg(feat4 + (size_t)sj * (F_DIM / 4) + lane);
                wsum[i] += w;
                acc[i].x = fmaf(w, ft.x, acc[i].x);
                acc[i].y = fmaf(w, ft.y, acc[i].y);
                acc[i].z = fmaf(w, ft.z, acc[i].z);
                acc[i].w = fmaf(w, ft.w, acc[i].w);
            }
        }
    }

    // normalize + write
    #pragma unroll
    for (int i = 0; i < UPW; i++) {
        int u = u0 + i;
        if (u >= NUP) break;
        float ws  = (wsum[i] > 0.0f) ? wsum[i] : 0.001f;
        float inv = 1.0f / ws;
        float4 o  = make_float4(acc[i].x * inv, acc[i].y * inv,
                                acc[i].z * inv, acc[i].w * inv);
        __stcs((float4*)(out + (size_t)u * F_DIM) + lane, o);
    }
}

// ---------------------------------------------------------------------------
extern "C" void kernel_launch(void* const* d_in, const int* in_sizes, int n_in,
                              void* d_out, int out_size) {
    const float* feat = (const float*)d_in[0];   // (N, 128) f32
    const float* wdn  = (const float*)d_in[1];   // (N, 5)   f32
    const int*   nidx = (const int*)  d_in[2];   // (N, 5)   i32
    const int*   sel  = (const int*)  d_in[3];   // (NUP, 1) i32
    float* out = (float*)d_out;                  // (NUP, 128) f32

    // K0: reset counters to "unselected"
    {
        int n4 = N_NODES / 4;
        k_clear_cnt<<<(n4 + TPB - 1) / TPB, TPB>>>();
    }
    // K1: mark selected destinations
    k_mark<<<(NUP + TPB - 1) / TPB, TPB>>>(sel);

    // K2: bucket fill (thread per contribution, selected dsts only)
    k_fill<<<(NCONTRIB + TPB - 1) / TPB, TPB>>>(wdn, nidx);

    // K3: fused gather + normalize (4 output rows per warp)
    {
        int warps  = (NUP + UPW - 1) / UPW;          // 25000
        long long thr = (long long)warps * 32;
        k_gather_fused<<<(int)((thr + TPB - 1) / TPB), TPB>>>(sel, feat, out);
    }
}

// round 16
// speedup vs baseline: 1.8164x; 1.8164x over previous
#include <cuda_runtime.h>

// Problem shape (fixed for this dataset)
#define N_NODES 400000
#define K_DOWN  5
#define NCONTRIB (N_NODES * K_DOWN)   // 2,000,000
#define F_DIM   128
#define NUP     100000
#define CAP     32                    // bucket capacity per destination
#define UNSEL   (-2147483647 - 1)     // INT_MIN: counter value for unselected rows
#define UPW     4                     // outputs per warp in the gather
#define TPB     256

// Scratch (allocation-free rule: __device__ globals)
// entry = (w:f32 << 32) | src:u32 ; 400k * 32 * 8B = 102.4 MB
__device__ unsigned long long g_ent[(size_t)N_NODES * CAP];
__device__ int                g_cnt[N_NODES];

// ---------------------------------------------------------------------------
// K0: reset counters to INT_MIN ("not selected"). 32B per thread.
__global__ void k_clear_cnt() {
    int i = blockIdx.x * blockDim.x + threadIdx.x;
    const int n8 = N_NODES / 8;           // 50000 threads, 2x int4 each
    if (i < n8) {
        int4 v = make_int4(UNSEL, UNSEL, UNSEL, UNSEL);
        ((int4*)g_cnt)[i * 2 + 0] = v;
        ((int4*)g_cnt)[i * 2 + 1] = v;
    }
}

// K1: mark selected destinations: counter -> 0. Duplicate writes benign.
__global__ void k_mark(const int* __restrict__ sel) {
    int t = blockIdx.x * blockDim.x + threadIdx.x;
    if (t >= NUP) return;
    int s = sel[t];
    if (s >= 0 && s < N_NODES) g_cnt[s] = 0;
}

// K2: bucket fill — thread per (n,k) contribution. ONE 32-bit atomic per
// contribution; slot >= 0 only for selected destinations (unselected
// counters start at INT_MIN), so ~78% of scattered stores are skipped.
__global__ void k_fill(const float* __restrict__ wdn,
                       const int*   __restrict__ nidx) {
    int t = blockIdx.x * blockDim.x + threadIdx.x;
    if (t >= NCONTRIB) return;
    int dst = nidx[t];
    if (dst < 0 || dst >= N_NODES) return;
    int pos = atomicAdd(&g_cnt[dst], 1);
    if (pos >= 0 && pos < CAP) {
        float w  = wdn[t];
        int src  = t / K_DOWN;
        unsigned long long e =
            ((unsigned long long)__float_as_uint(w) << 32) | (unsigned int)src;
        g_ent[(size_t)dst * CAP + pos] = e;
    }
}

// K3: fused gather + normalize — FOUR output rows per warp.
// EXACT round-12 proven structure (SHFL broadcast, default-cached feature
// loads so dummy row-0 slots stay L1-resident — round 15 proved __ldcg /
// smem staging here is catastrophic). Only change: 32-bit byte-offset
// address math for the feature loads (max offset 204.8MB < 2^31).
__global__ void k_gather_fused(const int*   __restrict__ sel,
                               const float* __restrict__ feat,
                               float*       __restrict__ out) {
    int warp = (blockIdx.x * blockDim.x + threadIdx.x) >> 5;
    int u0 = warp * UPW;
    if (u0 >= NUP) return;
    int lane = threadIdx.x & 31;
    int grp  = lane >> 3;          // which of the 4 outputs this lane serves
    int slot = lane & 7;           // bucket slot 0..7

    // uniform scalar loads: all lanes hold all four (s, c)
    int s[UPW], c[UPW];
    #pragma unroll
    for (int i = 0; i < UPW; i++) {
        int u = u0 + i;
        int sv = (u < NUP) ? sel[u] : -1;
        s[i] = (sv >= 0 && sv < N_NODES) ? sv : -1;
    }
    #pragma unroll
    for (int i = 0; i < UPW; i++) {
        int cv = (s[i] >= 0) ? g_cnt[s[i]] : 0;
        if (cv < 0)   cv = 0;
        if (cv > CAP) cv = CAP;
        c[i] = cv;
    }

    // one coalesced trip: slots 0..7 of all four buckets
    int sg = s[grp];
    unsigned long long ev = (sg >= 0)
        ? __ldcs(g_ent + (size_t)sg * CAP + slot) : 0ull;

    const char* featb = (const char*)feat;
    unsigned laneoff = (unsigned)(lane * 16);
    float  wsum[UPW];
    float4 acc [UPW];
    #pragma unroll
    for (int i = 0; i < UPW; i++) {
        wsum[i] = 0.0f;
        acc[i]  = make_float4(0.f, 0.f, 0.f, 0.f);
    }

    #pragma unroll
    for (int j = 0; j < 8; j++) {
        float  wj[UPW];
        float4 f [UPW];
        #pragma unroll
        for (int i = 0; i < UPW; i++) {
            unsigned long long e = __shfl_sync(0xffffffffu, ev, i * 8 + j);
            bool v  = (j < c[i]);
            unsigned sj = v ? (unsigned)(e & 0xffffffffull) : 0u;
            wj[i]   = v ? __uint_as_float((unsigned int)(e >> 32)) : 0.0f;
            f[i] = *(const float4*)(featb + (sj * 512u + laneoff));
        }
        #pragma unroll
        for (int i = 0; i < UPW; i++) {
            wsum[i] += wj[i];
            acc[i].x = fmaf(wj[i], f[i].x, acc[i].x);
            acc[i].y = fmaf(wj[i], f[i].y, acc[i].y);
            acc[i].z = fmaf(wj[i], f[i].z, acc[i].z);
            acc[i].w = fmaf(wj[i], f[i].w, acc[i].w);
        }
    }

    // rare tail: c > 8 (P ~ 7% per output)
    #pragma unroll
    for (int i = 0; i < UPW; i++) {
        if (c[i] > 8) {
            const unsigned long long* bucket = g_ent + (size_t)s[i] * CAP;
            for (int j = 8; j < c[i]; j++) {
                unsigned long long e = __ldcs(bucket + j);  // uniform broadcast
                unsigned sj = (unsigned)(e & 0xffffffffull);
                float w  = __uint_as_float((unsigned int)(e >> 32));
                float4 ft = *(const float4*)(featb + (sj * 512u + laneoff));
                wsum[i] += w;
                acc[i].x = fmaf(w, ft.x, acc[i].x);
                acc[i].y = fmaf(w, ft.y, acc[i].y);
                acc[i].z = fmaf(w, ft.z, acc[i].z);
                acc[i].w = fmaf(w, ft.w, acc[i].w);
            }
        }
    }

    // normalize + write
    #pragma unroll
    for (int i = 0; i < UPW; i++) {
        int u = u0 + i;
        if (u >= NUP) break;
        float ws  = (wsum[i] > 0.0f) ? wsum[i] : 0.001f;
        float inv = 1.0f / ws;
        float4 o  = make_float4(acc[i].x * inv, acc[i].y * inv,
                                acc[i].z * inv, acc[i].w * inv);
        __stcs((float4*)(out + (size_t)u * F_DIM) + lane, o);
    }
}

// ---------------------------------------------------------------------------
extern "C" void kernel_launch(void* const* d_in, const int* in_sizes, int n_in,
                              void* d_out, int out_size) {
    const float* feat = (const float*)d_in[0];   // (N, 128) f32
    const float* wdn  = (const float*)d_in[1];   // (N, 5)   f32
    const int*   nidx = (const int*)  d_in[2];   // (N, 5)   i32
    const int*   sel  = (const int*)  d_in[3];   // (NUP, 1) i32
    float* out = (float*)d_out;                  // (NUP, 128) f32

    // K0: reset counters to "unselected"
    {
        int n8 = N_NODES / 8;
        k_clear_cnt<<<(n8 + TPB - 1) / TPB, TPB>>>();
    }
    // K1: mark selected destinations
    k_mark<<<(NUP + TPB - 1) / TPB, TPB>>>(sel);

    // K2: bucket fill (thread per contribution, selected dsts only)
    k_fill<<<(NCONTRIB + TPB - 1) / TPB, TPB>>>(wdn, nidx);

    // K3: fused gather + normalize (4 output rows per warp)
    {
        int warps  = (NUP + UPW - 1) / UPW;          // 25000
        long long thr = (long long)warps * 32;
        k_gather_fused<<<(int)((thr + TPB - 1) / TPB), TPB>>>(sel, feat, out);
    }
}

// round 17
// speedup vs baseline: 1.8637x; 1.0260x over previous
#include <cuda_runtime.h>

// Problem shape (fixed for this dataset)
#define N_NODES 400000
#define K_DOWN  5
#define NCONTRIB (N_NODES * K_DOWN)   // 2,000,000
#define F_DIM   128
#define NUP     100000
#define CAP     32                    // bucket capacity per destination
#define UNSEL   (-2147483647 - 1)     // INT_MIN: counter value for unselected rows
#define UPW     4                     // outputs per warp in the gather
#define TPB     256

// Scratch (allocation-free rule: __device__ globals)
// entry = (w:f32 << 32) | src:u32 ; 400k * 32 * 8B = 102.4 MB
__device__ unsigned long long g_ent[(size_t)N_NODES * CAP];
__device__ int                g_cnt[N_NODES];

// ---------------------------------------------------------------------------
// K0: reset counters to INT_MIN ("not selected"). 32B per thread.
__global__ void k_clear_cnt() {
    int i = blockIdx.x * blockDim.x + threadIdx.x;
    const int n8 = N_NODES / 8;
    if (i < n8) {
        int4 v = make_int4(UNSEL, UNSEL, UNSEL, UNSEL);
        ((int4*)g_cnt)[i * 2 + 0] = v;
        ((int4*)g_cnt)[i * 2 + 1] = v;
    }
}

// K1: mark selected destinations: counter -> 0. Duplicate writes benign.
__global__ void k_mark(const int* __restrict__ sel) {
    int t = blockIdx.x * blockDim.x + threadIdx.x;
    if (t >= NUP) return;
    int s = sel[t];
    if (s >= 0 && s < N_NODES) g_cnt[s] = 0;
}

// K2: bucket fill — thread per (n,k) contribution. ONE 32-bit atomic per
// contribution; slot >= 0 only for selected destinations (unselected
// counters start at INT_MIN), so ~78% of scattered stores are skipped.
__global__ void k_fill(const float* __restrict__ wdn,
                       const int*   __restrict__ nidx) {
    int t = blockIdx.x * blockDim.x + threadIdx.x;
    if (t >= NCONTRIB) return;
    int dst = nidx[t];
    if (dst < 0 || dst >= N_NODES) return;
    int pos = atomicAdd(&g_cnt[dst], 1);
    if (pos >= 0 && pos < CAP) {
        float w  = wdn[t];
        int src  = t / K_DOWN;
        unsigned long long e =
            ((unsigned long long)__float_as_uint(w) << 32) | (unsigned int)src;
        g_ent[(size_t)dst * CAP + pos] = e;
    }
}

// K3: fused gather + normalize — FOUR output rows per warp, j-steps taken in
// PAIRS: all 8 feature LDG.128 of a pair issue before any FMA consumes them
// -> per-warp MLP ~8 (was ~4; round-16 analysis showed concurrency x latency
// is the binding constraint at DRAM=52%). Dummy slots read row 0
// (L1-resident, proven cheap); SHFL broadcast (round-15 proved smem/ldcg
// variants regress). __launch_bounds__(256,4) holds 4 blocks/SM.
__global__ void __launch_bounds__(TPB, 4)
k_gather_fused(const int*   __restrict__ sel,
               const float* __restrict__ feat,
               float*       __restrict__ out) {
    int warp = (blockIdx.x * blockDim.x + threadIdx.x) >> 5;
    int u0 = warp * UPW;
    if (u0 >= NUP) return;
    int lane = threadIdx.x & 31;
    int grp  = lane >> 3;          // which of the 4 outputs this lane serves
    int slot = lane & 7;           // bucket slot 0..7

    // uniform scalar loads: all lanes hold all four (s, c)
    int s[UPW], c[UPW];
    #pragma unroll
    for (int i = 0; i < UPW; i++) {
        int u = u0 + i;
        int sv = (u < NUP) ? sel[u] : -1;
        s[i] = (sv >= 0 && sv < N_NODES) ? sv : -1;
    }
    #pragma unroll
    for (int i = 0; i < UPW; i++) {
        int cv = (s[i] >= 0) ? g_cnt[s[i]] : 0;
        if (cv < 0)   cv = 0;
        if (cv > CAP) cv = CAP;
        c[i] = cv;
    }

    // one coalesced trip: slots 0..7 of all four buckets
    int sg = s[grp];
    unsigned long long ev = (sg >= 0)
        ? __ldcs(g_ent + (size_t)sg * CAP + slot) : 0ull;

    const char* featb = (const char*)feat;
    unsigned laneoff = (unsigned)(lane * 16);
    float  wsum[UPW];
    float4 acc [UPW];
    #pragma unroll
    for (int i = 0; i < UPW; i++) {
        wsum[i] = 0.0f;
        acc[i]  = make_float4(0.f, 0.f, 0.f, 0.f);
    }

    #pragma unroll
    for (int jp = 0; jp < 4; jp++) {
        float  wj[2][UPW];
        float4 f [2][UPW];
        // ---- issue ALL 8 loads of this pair before any consumer ----
        #pragma unroll
        for (int h = 0; h < 2; h++) {
            int j = jp * 2 + h;
            #pragma unroll
            for (int i = 0; i < UPW; i++) {
                unsigned long long e = __shfl_sync(0xffffffffu, ev, i * 8 + j);
                bool v  = (j < c[i]);
                unsigned sj = v ? (unsigned)(e & 0xffffffffull) : 0u;
                wj[h][i] = v ? __uint_as_float((unsigned int)(e >> 32)) : 0.0f;
                f[h][i]  = *(const float4*)(featb + (sj * 512u + laneoff));
            }
        }
        // ---- consume ----
        #pragma unroll
        for (int h = 0; h < 2; h++) {
            #pragma unroll
            for (int i = 0; i < UPW; i++) {
                wsum[i] += wj[h][i];
                acc[i].x = fmaf(wj[h][i], f[h][i].x, acc[i].x);
                acc[i].y = fmaf(wj[h][i], f[h][i].y, acc[i].y);
                acc[i].z = fmaf(wj[h][i], f[h][i].z, acc[i].z);
                acc[i].w = fmaf(wj[h][i], f[h][i].w, acc[i].w);
            }
        }
    }

    // rare tail: c > 8 (P ~ 7% per output)
    #pragma unroll
    for (int i = 0; i < UPW; i++) {
        if (c[i] > 8) {
            const unsigned long long* bucket = g_ent + (size_t)s[i] * CAP;
            for (int j = 8; j < c[i]; j++) {
                unsigned long long e = __ldcs(bucket + j);  // uniform broadcast
                unsigned sj = (unsigned)(e & 0xffffffffull);
                float w  = __uint_as_float((unsigned int)(e >> 32));
                float4 ft = *(const float4*)(featb + (sj * 512u + laneoff));
                wsum[i] += w;
                acc[i].x = fmaf(w, ft.x, acc[i].x);
                acc[i].y = fmaf(w, ft.y, acc[i].y);
                acc[i].z = fmaf(w, ft.z, acc[i].z);
                acc[i].w = fmaf(w, ft.w, acc[i].w);
            }
        }
    }

    // normalize + write
    #pragma unroll
    for (int i = 0; i < UPW; i++) {
        int u = u0 + i;
        if (u >= NUP) break;
        float ws  = (wsum[i] > 0.0f) ? wsum[i] : 0.001f;
        float inv = 1.0f / ws;
        float4 o  = make_float4(acc[i].x * inv, acc[i].y * inv,
                                acc[i].z * inv, acc[i].w * inv);
        __stcs((float4*)(out + (size_t)u * F_DIM) + lane, o);
    }
}

// ---------------------------------------------------------------------------
extern "C" void kernel_launch(void* const* d_in, const int* in_sizes, int n_in,
                              void* d_out, int out_size) {
    const float* feat = (const float*)d_in[0];   // (N, 128) f32
    const float* wdn  = (const float*)d_in[1];   // (N, 5)   f32
    const int*   nidx = (const int*)  d_in[2];   // (N, 5)   i32
    const int*   sel  = (const int*)  d_in[3];   // (NUP, 1) i32
    float* out = (float*)d_out;                  // (NUP, 128) f32

    // K0: reset counters to "unselected"
    {
        int n8 = N_NODES / 8;
        k_clear_cnt<<<(n8 + TPB - 1) / TPB, TPB>>>();
    }
    // K1: mark selected destinations
    k_mark<<<(NUP + TPB - 1) / TPB, TPB>>>(sel);

    // K2: bucket fill (thread per contribution, selected dsts only)
    k_fill<<<(NCONTRIB + TPB - 1) / TPB, TPB>>>(wdn, nidx);

    // K3: fused gather + normalize (4 output rows per warp, paired j-steps)
    {
        int warps  = (NUP + UPW - 1) / UPW;          // 25000
        long long thr = (long long)warps * 32;
        k_gather_fused<<<(int)((thr + TPB - 1) / TPB), TPB>>>(sel, feat, out);
    }
}